// round 14
// baseline (speedup 1.0000x reference)
#include <cuda_runtime.h>
#include <cstdint>

// Problem constants (fixed by the reference).
static constexpr int NU    = 100000;   // users
static constexpr int NI    = 50000;    // items
static constexpr int D     = 64;       // dim
static constexpr int NP    = 3;        // meta-paths
static constexpr int DEG   = 16;
static constexpr int EU    = NU * DEG; // edges per user path (1.6M)
static constexpr int EI    = NI * DEG; // edges per item path (0.8M)
static constexpr int BATCH = 8192;

static constexpr int UIDS     = BATCH;                // user id region [0, 8192)
static constexpr int MAXROWS  = 3 * BATCH;            // 24576 ids (items at [8192, 24576))
static constexpr int MAXSLOTS = MAXROWS * NP;         // 73728 (id, path) slots
static constexpr int CAP      = 64;                   // max edges per slot bin
static constexpr int BMW      = (NU + NI + 31) / 32;  // 4688 bitmap words (18.75 KB)

// Scratch (static device memory; ~57 MB total).
__device__ float              g_agg[(size_t)MAXSLOTS * D];    // 18.9 MB (fully written by process)
__device__ float              g_m[(size_t)MAXSLOTS * D];      // 18.9 MB per-path GEMM result
__device__ unsigned long long g_bin[(size_t)MAXSLOTS * CAP];  // 37.7 MB
__device__ int                g_cnt[MAXSLOTS];                // 295 KB
__device__ int                g_rowid[NU + NI];               // 600 KB (-1 = not live)
__device__ unsigned           g_bitmap[BMW];                  // 18.75 KB
__device__ int                g_nlive_u;
__device__ int                g_nlive_i;

static inline unsigned cdiv(long long a, long long b) { return (unsigned)((a + b - 1) / b); }

// ---------------------------------------------------------------------------
// K0: clear rowid map, bitmap, bin cursors, live counters (no agg zero)
// ---------------------------------------------------------------------------
__global__ void __launch_bounds__(256) k_clear() {
    int t = blockIdx.x * blockDim.x + threadIdx.x;
    if (t < NU + NI) g_rowid[t] = -1;
    int b = t - (NU + NI);
    if (b >= 0 && b < BMW) g_bitmap[b] = 0u;
    int c = t - (NU + NI + BMW);
    if (c >= 0 && c < MAXSLOTS) g_cnt[c] = 0;
    if (t == 0) { g_nlive_u = 0; g_nlive_i = 0; }
}

// ---------------------------------------------------------------------------
// K1: flag rows: bitmap bit + CAS-claim side-partitioned compact id
// ---------------------------------------------------------------------------
__global__ void __launch_bounds__(256) k_flags(const int* __restrict__ ui,
                                               const int* __restrict__ ii,
                                               const int* __restrict__ ni) {
    int t = blockIdx.x * blockDim.x + threadIdx.x;
    int rg; bool user;
    if (t < BATCH)          { rg = ui[t];                user = true;  }
    else if (t < 2 * BATCH) { rg = NU + ii[t - BATCH];   user = false; }
    else if (t < 3 * BATCH) { rg = NU + ni[t - 2*BATCH]; user = false; }
    else return;

    atomicOr(&g_bitmap[rg >> 5], 1u << (rg & 31));
    if (atomicCAS(&g_rowid[rg], -1, -2) == -1) {
        int id = user ? atomicAdd(&g_nlive_u, 1)
                      : (UIDS + atomicAdd(&g_nlive_i, 1));
        g_rowid[rg] = id;
    }
}

// ---------------------------------------------------------------------------
// K2: bin pass.  SMEM bitmap filter; 8 edges/thread (2 x int4 metadata groups
//     per iteration for doubled stream MLP); survivors drop packed (val,col).
// ---------------------------------------------------------------------------
__device__ __forceinline__ void bin_group4(const unsigned* sbm, int e, int p, int roff,
                                           const int* __restrict__ rows,
                                           const int* __restrict__ cols,
                                           const float* __restrict__ vals) {
    int4 r4 = __ldg(reinterpret_cast<const int4*>(rows + e));
    int x0 = roff + r4.x, x1 = roff + r4.y, x2 = roff + r4.z, x3 = roff + r4.w;
    unsigned b0 = (sbm[x0 >> 5] >> (x0 & 31)) & 1u;
    unsigned b1 = (sbm[x1 >> 5] >> (x1 & 31)) & 1u;
    unsigned b2 = (sbm[x2 >> 5] >> (x2 & 31)) & 1u;
    unsigned b3 = (sbm[x3 >> 5] >> (x3 & 31)) & 1u;
    if (!(b0 | b1 | b2 | b3)) return;

    int4   c4 = __ldg(reinterpret_cast<const int4*>(cols + e));
    float4 v4 = __ldg(reinterpret_cast<const float4*>(vals + e));

    if (b0) {
        int slot = g_rowid[x0] * NP + p;
        int pos = atomicAdd(&g_cnt[slot], 1);
        if (pos < CAP)
            g_bin[(size_t)slot * CAP + pos] =
                ((unsigned long long)__float_as_uint(v4.x) << 32) | (unsigned)c4.x;
    }
    if (b1) {
        int slot = g_rowid[x1] * NP + p;
        int pos = atomicAdd(&g_cnt[slot], 1);
        if (pos < CAP)
            g_bin[(size_t)slot * CAP + pos] =
                ((unsigned long long)__float_as_uint(v4.y) << 32) | (unsigned)c4.y;
    }
    if (b2) {
        int slot = g_rowid[x2] * NP + p;
        int pos = atomicAdd(&g_cnt[slot], 1);
        if (pos < CAP)
            g_bin[(size_t)slot * CAP + pos] =
                ((unsigned long long)__float_as_uint(v4.z) << 32) | (unsigned)c4.z;
    }
    if (b3) {
        int slot = g_rowid[x3] * NP + p;
        int pos = atomicAdd(&g_cnt[slot], 1);
        if (pos < CAP)
            g_bin[(size_t)slot * CAP + pos] =
                ((unsigned long long)__float_as_uint(v4.w) << 32) | (unsigned)c4.w;
    }
}

__global__ void __launch_bounds__(256) k_bin(const int*   __restrict__ u_rows,
                                             const int*   __restrict__ u_cols,
                                             const float* __restrict__ u_vals,
                                             const int*   __restrict__ i_rows,
                                             const int*   __restrict__ i_cols,
                                             const float* __restrict__ i_vals) {
    __shared__ unsigned sbm[BMW];                // 18752 B
    for (int i = threadIdx.x; i < BMW; i += blockDim.x) sbm[i] = g_bitmap[i];
    __syncthreads();

    constexpr long long NG = (long long)NP * (EU + EI) / 8;   // 900k groups of 8
    const long long stride = (long long)gridDim.x * blockDim.x;

    for (long long g = (long long)blockIdx.x * blockDim.x + threadIdx.x;
         g < NG; g += stride) {
        long long e0 = g * 8;
        const int* rows; const int* cols; const float* vals;
        int e, p, roff;
        if (e0 < (long long)NP * EU) {
            e = (int)e0;  p = e / EU;
            rows = u_rows; cols = u_cols; vals = u_vals; roff = 0;
        } else {
            e = (int)(e0 - (long long)NP * EU);  p = e / EI;
            rows = i_rows; cols = i_cols; vals = i_vals; roff = NU;
        }
        // 8 consecutive edges never cross a path boundary (EU, EI % 8 == 0)
        bin_group4(sbm, e,     p, roff, rows, cols, vals);
        bin_group4(sbm, e + 4, p, roff, rows, cols, vals);
    }
}

// ---------------------------------------------------------------------------
// K3: per-slot reduction.  One warp per live (id,path) slot.  Per 32-entry
//     chunk: ONE coalesced bin load, then steps of 4 with FOUR independent
//     accumulator pairs and 4 LDG.64 gathers in flight.
// ---------------------------------------------------------------------------
__global__ void __launch_bounds__(128) k_process(const float* __restrict__ u_table,
                                                 const float* __restrict__ i_table) {
    int slot = blockIdx.x * (blockDim.x >> 5) + (threadIdx.x >> 5);
    if (slot >= MAXSLOTS) return;
    int id = slot / NP;
    bool user = id < UIDS;
    int live = user ? g_nlive_u : g_nlive_i;
    if ((user ? id : (id - UIDS)) >= live) return;

    int lane = threadIdx.x & 31;
    const float* table = user ? u_table : i_table;
    int n = min(g_cnt[slot], CAP);
    const unsigned long long* bin = g_bin + (size_t)slot * CAP;

    float2 a0 = {0.f, 0.f}, a1 = {0.f, 0.f}, a2 = {0.f, 0.f}, a3 = {0.f, 0.f};
    for (int base = 0; base < n; base += 32) {
        int m = min(32, n - base);
        unsigned long long pk = (lane < m) ? __ldg(bin + base + lane) : 0ull;
        unsigned lo = (unsigned)pk;
        unsigned hi = (unsigned)(pk >> 32);
        int k = 0;
        for (; k + 3 < m; k += 4) {
            unsigned c0 = __shfl_sync(0xffffffffu, lo, k);
            unsigned c1 = __shfl_sync(0xffffffffu, lo, k + 1);
            unsigned c2 = __shfl_sync(0xffffffffu, lo, k + 2);
            unsigned c3 = __shfl_sync(0xffffffffu, lo, k + 3);
            float v0 = __uint_as_float(__shfl_sync(0xffffffffu, hi, k));
            float v1 = __uint_as_float(__shfl_sync(0xffffffffu, hi, k + 1));
            float v2 = __uint_as_float(__shfl_sync(0xffffffffu, hi, k + 2));
            float v3 = __uint_as_float(__shfl_sync(0xffffffffu, hi, k + 3));
            float2 t0 = __ldg(reinterpret_cast<const float2*>(table + (size_t)c0 * D) + lane);
            float2 t1 = __ldg(reinterpret_cast<const float2*>(table + (size_t)c1 * D) + lane);
            float2 t2 = __ldg(reinterpret_cast<const float2*>(table + (size_t)c2 * D) + lane);
            float2 t3 = __ldg(reinterpret_cast<const float2*>(table + (size_t)c3 * D) + lane);
            a0.x += v0 * t0.x; a0.y += v0 * t0.y;
            a1.x += v1 * t1.x; a1.y += v1 * t1.y;
            a2.x += v2 * t2.x; a2.y += v2 * t2.y;
            a3.x += v3 * t3.x; a3.y += v3 * t3.y;
        }
        for (; k < m; k++) {
            unsigned c = __shfl_sync(0xffffffffu, lo, k);
            float    v = __uint_as_float(__shfl_sync(0xffffffffu, hi, k));
            float2 t = __ldg(reinterpret_cast<const float2*>(table + (size_t)c * D) + lane);
            a0.x += v * t.x; a0.y += v * t.y;
        }
    }
    float2 acc;
    acc.x = (a0.x + a1.x) + (a2.x + a3.x);
    acc.y = (a0.y + a1.y) + (a2.y + a3.y);
    reinterpret_cast<float2*>(g_agg + (size_t)slot * D)[lane] = acc;
}

// ---------------------------------------------------------------------------
// K4: dense per-path GEMM over the compact id space (proven round-12 shape).
// ---------------------------------------------------------------------------
static constexpr int TROWS = 64;
static constexpr int SPAD  = 68;

__global__ void __launch_bounds__(256) k_gemm(const float* __restrict__ Wu,
                                              const float* __restrict__ Wi) {
    __shared__ float As[D * SPAD];
    __shared__ float Ws[D * SPAD];

    int rb = blockIdx.x / NP;
    int p  = blockIdx.x % NP;
    int id0 = rb * TROWS;
    bool user = (id0 < UIDS);
    int livecnt = user ? g_nlive_u : g_nlive_i;
    if ((user ? id0 : (id0 - UIDS)) >= livecnt) return;

    const float* W = (user ? Wu : Wi) + p * D * D;
    int tid = threadIdx.x;

    #pragma unroll
    for (int j = tid; j < D * D; j += 256) {
        int k = j >> 6, c = j & 63;
        Ws[k * SPAD + c] = __ldg(W + j);
    }
    #pragma unroll
    for (int j = tid; j < TROWS * D; j += 256) {
        int r = j >> 6, k = j & 63;
        As[k * SPAD + r] = g_agg[(size_t)((id0 + r) * NP + p) * D + k];
    }
    __syncthreads();

    int tx = tid & 15, ty = tid >> 4;
    int c0 = tx * 4, r0 = ty * 4;

    float m[4][4];
    #pragma unroll
    for (int i = 0; i < 4; i++)
        #pragma unroll
        for (int j = 0; j < 4; j++) m[i][j] = 0.f;

    #pragma unroll
    for (int k = 0; k < D; k++) {
        float4 a = *reinterpret_cast<const float4*>(&As[k * SPAD + r0]);
        float4 b = *reinterpret_cast<const float4*>(&Ws[k * SPAD + c0]);
        float av[4] = {a.x, a.y, a.z, a.w};
        float bv[4] = {b.x, b.y, b.z, b.w};
        #pragma unroll
        for (int i = 0; i < 4; i++)
            #pragma unroll
            for (int j = 0; j < 4; j++)
                m[i][j] += av[i] * bv[j];
    }

    #pragma unroll
    for (int i = 0; i < 4; i++) {
        float4 o4 = make_float4(m[i][0], m[i][1], m[i][2], m[i][3]);
        *reinterpret_cast<float4*>(
            &g_m[(size_t)((id0 + r0 + i) * NP + p) * D + c0]) = o4;
    }
}

// ---------------------------------------------------------------------------
// K5: combine (proven round-12 shape).
// ---------------------------------------------------------------------------
__global__ void __launch_bounds__(256) k_comb(const float* __restrict__ wb1,
                                              const float* __restrict__ wb2,
                                              const int*   __restrict__ ui,
                                              const int*   __restrict__ ii,
                                              const int*   __restrict__ ni,
                                              float*       __restrict__ out) {
    int t = blockIdx.x * blockDim.x + threadIdx.x;
    int row = t >> 4, q = t & 15;
    if (row >= 3 * BATCH) return;
    int seg = row / BATCH, b = row % BATCH;

    const int*   idxA = (seg == 0) ? ui : ((seg == 1) ? ii : ni);
    const float* wbp  = (seg == 0) ? wb1 : wb2;
    int roff = (seg == 0) ? 0 : NU;

    int id = g_rowid[roff + __ldg(idxA + b)];
    float w0 = __ldg(wbp + 0), w1 = __ldg(wbp + 1), w2 = __ldg(wbp + 2);

    const float* mb = g_m + (size_t)id * NP * D + q * 4;
    float4 m0 = *reinterpret_cast<const float4*>(mb);
    float4 m1 = *reinterpret_cast<const float4*>(mb + D);
    float4 m2 = *reinterpret_cast<const float4*>(mb + 2 * D);

    float4 o;
    o.x = fmaxf(w0 * fmaxf(m0.x, 0.f) + w1 * fmaxf(m1.x, 0.f) + w2 * fmaxf(m2.x, 0.f), 0.f);
    o.y = fmaxf(w0 * fmaxf(m0.y, 0.f) + w1 * fmaxf(m1.y, 0.f) + w2 * fmaxf(m2.y, 0.f), 0.f);
    o.z = fmaxf(w0 * fmaxf(m0.z, 0.f) + w1 * fmaxf(m1.z, 0.f) + w2 * fmaxf(m2.z, 0.f), 0.f);
    o.w = fmaxf(w0 * fmaxf(m0.w, 0.f) + w1 * fmaxf(m1.w, 0.f) + w2 * fmaxf(m2.w, 0.f), 0.f);

    *reinterpret_cast<float4*>(out + ((size_t)seg * BATCH + b) * D + q * 4) = o;
}

// ---------------------------------------------------------------------------
// Launch
// ---------------------------------------------------------------------------
extern "C" void kernel_launch(void* const* d_in, const int* in_sizes, int n_in,
                              void* d_out, int out_size) {
    const float* user_table = (const float*)d_in[0];
    const float* item_table = (const float*)d_in[1];
    const float* Wu         = (const float*)d_in[2];
    const float* Wi         = (const float*)d_in[3];
    const float* wb1        = (const float*)d_in[4];
    const float* wb2        = (const float*)d_in[5];
    const float* user_vals  = (const float*)d_in[6];
    const float* item_vals  = (const float*)d_in[7];
    const int*   user_rows  = (const int*)d_in[8];
    const int*   user_cols  = (const int*)d_in[9];
    const int*   item_rows  = (const int*)d_in[10];
    const int*   item_cols  = (const int*)d_in[11];
    const int*   user_idx   = (const int*)d_in[12];
    const int*   item_idx   = (const int*)d_in[13];
    const int*   neg_idx    = (const int*)d_in[14];
    float* out = (float*)d_out;

    k_clear<<<cdiv(NU + NI + BMW + MAXSLOTS, 256), 256>>>();
    k_flags<<<cdiv(3 * BATCH, 256), 256>>>(user_idx, item_idx, neg_idx);
    k_bin<<<1184, 256>>>(user_rows, user_cols, user_vals,
                         item_rows, item_cols, item_vals);
    k_process<<<cdiv(MAXSLOTS, 4), 128>>>(user_table, item_table);
    k_gemm<<<(MAXROWS / TROWS) * NP, 256>>>(Wu, Wi);
    k_comb<<<cdiv(3 * BATCH * 16, 256), 256>>>(wb1, wb2, user_idx, item_idx, neg_idx, out);
}

// round 15
// speedup vs baseline: 1.2529x; 1.2529x over previous
#include <cuda_runtime.h>
#include <cstdint>

// Problem constants (fixed by the reference).
static constexpr int NU    = 100000;   // users
static constexpr int NI    = 50000;    // items
static constexpr int D     = 64;       // dim
static constexpr int NP    = 3;        // meta-paths
static constexpr int DEG   = 16;
static constexpr int EU    = NU * DEG; // edges per user path (1.6M)
static constexpr int EI    = NI * DEG; // edges per item path (0.8M)
static constexpr int BATCH = 8192;

static constexpr int UIDS     = BATCH;                // user id region [0, 8192)
static constexpr int MAXROWS  = 3 * BATCH;            // 24576 ids (items at [8192, 24576))
static constexpr int MAXSLOTS = MAXROWS * NP;         // 73728 (id, path) slots
static constexpr int CAP      = 64;                   // max edges per slot bin
static constexpr int BMW      = (NU + NI + 31) / 32;  // 4688 bitmap words (18.75 KB)

// Scratch (static device memory; ~57 MB total).
__device__ float              g_agg[(size_t)MAXSLOTS * D];    // 18.9 MB (fully written by process)
__device__ float              g_m[(size_t)MAXSLOTS * D];      // 18.9 MB per-path GEMM result
__device__ unsigned long long g_bin[(size_t)MAXSLOTS * CAP];  // 37.7 MB
__device__ int                g_cnt[MAXSLOTS];                // 295 KB
__device__ int                g_rowid[NU + NI];               // 600 KB (-1 = not live)
__device__ unsigned           g_bitmap[BMW];                  // 18.75 KB
__device__ int                g_nlive_u;
__device__ int                g_nlive_i;

static inline unsigned cdiv(long long a, long long b) { return (unsigned)((a + b - 1) / b); }

// ---------------------------------------------------------------------------
// K0: clear rowid map, bitmap, bin cursors, live counters (no agg zero)
// ---------------------------------------------------------------------------
__global__ void __launch_bounds__(256) k_clear() {
    int t = blockIdx.x * blockDim.x + threadIdx.x;
    if (t < NU + NI) g_rowid[t] = -1;
    int b = t - (NU + NI);
    if (b >= 0 && b < BMW) g_bitmap[b] = 0u;
    int c = t - (NU + NI + BMW);
    if (c >= 0 && c < MAXSLOTS) g_cnt[c] = 0;
    if (t == 0) { g_nlive_u = 0; g_nlive_i = 0; }
}

// ---------------------------------------------------------------------------
// K1: flag rows: bitmap bit + CAS-claim side-partitioned compact id
// ---------------------------------------------------------------------------
__global__ void __launch_bounds__(256) k_flags(const int* __restrict__ ui,
                                               const int* __restrict__ ii,
                                               const int* __restrict__ ni) {
    int t = blockIdx.x * blockDim.x + threadIdx.x;
    int rg; bool user;
    if (t < BATCH)          { rg = ui[t];                user = true;  }
    else if (t < 2 * BATCH) { rg = NU + ii[t - BATCH];   user = false; }
    else if (t < 3 * BATCH) { rg = NU + ni[t - 2*BATCH]; user = false; }
    else return;

    atomicOr(&g_bitmap[rg >> 5], 1u << (rg & 31));
    if (atomicCAS(&g_rowid[rg], -1, -2) == -1) {
        int id = user ? atomicAdd(&g_nlive_u, 1)
                      : (UIDS + atomicAdd(&g_nlive_i, 1));
        g_rowid[rg] = id;
    }
}

// ---------------------------------------------------------------------------
// K2: bin pass (round-13 proven shape).  SMEM bitmap filter; 4 edges/thread
//     via int4 metadata loads; survivors drop packed (val,col) into bins.
// ---------------------------------------------------------------------------
__global__ void __launch_bounds__(256) k_bin(const int*   __restrict__ u_rows,
                                             const int*   __restrict__ u_cols,
                                             const float* __restrict__ u_vals,
                                             const int*   __restrict__ i_rows,
                                             const int*   __restrict__ i_cols,
                                             const float* __restrict__ i_vals) {
    __shared__ unsigned sbm[BMW];                // 18752 B
    for (int i = threadIdx.x; i < BMW; i += blockDim.x) sbm[i] = g_bitmap[i];
    __syncthreads();

    constexpr long long NG = (long long)NP * (EU + EI) / 4;   // 1.8M groups of 4
    const long long stride = (long long)gridDim.x * blockDim.x;

    for (long long g = (long long)blockIdx.x * blockDim.x + threadIdx.x;
         g < NG; g += stride) {
        long long e0 = g * 4;
        const int* rows; const int* cols; const float* vals;
        int e, p, roff;
        if (e0 < (long long)NP * EU) {
            e = (int)e0;  p = e / EU;
            rows = u_rows; cols = u_cols; vals = u_vals; roff = 0;
        } else {
            e = (int)(e0 - (long long)NP * EU);  p = e / EI;
            rows = i_rows; cols = i_cols; vals = i_vals; roff = NU;
        }

        int4 r4 = __ldg(reinterpret_cast<const int4*>(rows + e));
        int x0 = roff + r4.x, x1 = roff + r4.y, x2 = roff + r4.z, x3 = roff + r4.w;
        unsigned b0 = (sbm[x0 >> 5] >> (x0 & 31)) & 1u;
        unsigned b1 = (sbm[x1 >> 5] >> (x1 & 31)) & 1u;
        unsigned b2 = (sbm[x2 >> 5] >> (x2 & 31)) & 1u;
        unsigned b3 = (sbm[x3 >> 5] >> (x3 & 31)) & 1u;
        if (!(b0 | b1 | b2 | b3)) continue;

        int4   c4 = __ldg(reinterpret_cast<const int4*>(cols + e));
        float4 v4 = __ldg(reinterpret_cast<const float4*>(vals + e));

        if (b0) {
            int slot = g_rowid[x0] * NP + p;
            int pos = atomicAdd(&g_cnt[slot], 1);
            if (pos < CAP)
                g_bin[(size_t)slot * CAP + pos] =
                    ((unsigned long long)__float_as_uint(v4.x) << 32) | (unsigned)c4.x;
        }
        if (b1) {
            int slot = g_rowid[x1] * NP + p;
            int pos = atomicAdd(&g_cnt[slot], 1);
            if (pos < CAP)
                g_bin[(size_t)slot * CAP + pos] =
                    ((unsigned long long)__float_as_uint(v4.y) << 32) | (unsigned)c4.y;
        }
        if (b2) {
            int slot = g_rowid[x2] * NP + p;
            int pos = atomicAdd(&g_cnt[slot], 1);
            if (pos < CAP)
                g_bin[(size_t)slot * CAP + pos] =
                    ((unsigned long long)__float_as_uint(v4.z) << 32) | (unsigned)c4.z;
        }
        if (b3) {
            int slot = g_rowid[x3] * NP + p;
            int pos = atomicAdd(&g_cnt[slot], 1);
            if (pos < CAP)
                g_bin[(size_t)slot * CAP + pos] =
                    ((unsigned long long)__float_as_uint(v4.w) << 32) | (unsigned)c4.w;
        }
    }
}

// ---------------------------------------------------------------------------
// K3: per-slot reduction (round-13 proven shape).  One warp per live slot.
//     Per 32-entry chunk: ONE coalesced bin load across lanes, then
//     shuffle-broadcast each (col,val); inner loop `#pragma unroll 4`
//     (compiler-scheduled MLP at regs=32 / occ 84%).
// ---------------------------------------------------------------------------
__global__ void __launch_bounds__(128) k_process(const float* __restrict__ u_table,
                                                 const float* __restrict__ i_table) {
    int slot = blockIdx.x * (blockDim.x >> 5) + (threadIdx.x >> 5);
    if (slot >= MAXSLOTS) return;
    int id = slot / NP;
    bool user = id < UIDS;
    int live = user ? g_nlive_u : g_nlive_i;
    if ((user ? id : (id - UIDS)) >= live) return;

    int lane = threadIdx.x & 31;
    const float* table = user ? u_table : i_table;
    int n = min(g_cnt[slot], CAP);
    const unsigned long long* bin = g_bin + (size_t)slot * CAP;

    float2 acc = {0.f, 0.f};
    for (int base = 0; base < n; base += 32) {
        int m = min(32, n - base);
        unsigned long long pk = (lane < m) ? __ldg(bin + base + lane) : 0ull;
        unsigned lo = (unsigned)pk;
        unsigned hi = (unsigned)(pk >> 32);
        #pragma unroll 4
        for (int k = 0; k < m; k++) {
            unsigned c = __shfl_sync(0xffffffffu, lo, k);
            float    v = __uint_as_float(__shfl_sync(0xffffffffu, hi, k));
            float2 t = __ldg(reinterpret_cast<const float2*>(table + (size_t)c * D) + lane);
            acc.x += v * t.x;
            acc.y += v * t.y;
        }
    }
    reinterpret_cast<float2*>(g_agg + (size_t)slot * D)[lane] = acc;
}

// ---------------------------------------------------------------------------
// K4: dense per-path GEMM over the compact id space (proven round-12 shape).
// ---------------------------------------------------------------------------
static constexpr int TROWS = 64;
static constexpr int SPAD  = 68;

__global__ void __launch_bounds__(256) k_gemm(const float* __restrict__ Wu,
                                              const float* __restrict__ Wi) {
    __shared__ float As[D * SPAD];
    __shared__ float Ws[D * SPAD];

    int rb = blockIdx.x / NP;
    int p  = blockIdx.x % NP;
    int id0 = rb * TROWS;
    bool user = (id0 < UIDS);
    int livecnt = user ? g_nlive_u : g_nlive_i;
    if ((user ? id0 : (id0 - UIDS)) >= livecnt) return;

    const float* W = (user ? Wu : Wi) + p * D * D;
    int tid = threadIdx.x;

    #pragma unroll
    for (int j = tid; j < D * D; j += 256) {
        int k = j >> 6, c = j & 63;
        Ws[k * SPAD + c] = __ldg(W + j);
    }
    #pragma unroll
    for (int j = tid; j < TROWS * D; j += 256) {
        int r = j >> 6, k = j & 63;
        As[k * SPAD + r] = g_agg[(size_t)((id0 + r) * NP + p) * D + k];
    }
    __syncthreads();

    int tx = tid & 15, ty = tid >> 4;
    int c0 = tx * 4, r0 = ty * 4;

    float m[4][4];
    #pragma unroll
    for (int i = 0; i < 4; i++)
        #pragma unroll
        for (int j = 0; j < 4; j++) m[i][j] = 0.f;

    #pragma unroll
    for (int k = 0; k < D; k++) {
        float4 a = *reinterpret_cast<const float4*>(&As[k * SPAD + r0]);
        float4 b = *reinterpret_cast<const float4*>(&Ws[k * SPAD + c0]);
        float av[4] = {a.x, a.y, a.z, a.w};
        float bv[4] = {b.x, b.y, b.z, b.w};
        #pragma unroll
        for (int i = 0; i < 4; i++)
            #pragma unroll
            for (int j = 0; j < 4; j++)
                m[i][j] += av[i] * bv[j];
    }

    #pragma unroll
    for (int i = 0; i < 4; i++) {
        float4 o4 = make_float4(m[i][0], m[i][1], m[i][2], m[i][3]);
        *reinterpret_cast<float4*>(
            &g_m[(size_t)((id0 + r0 + i) * NP + p) * D + c0]) = o4;
    }
}

// ---------------------------------------------------------------------------
// K5: combine (proven round-12 shape).
// ---------------------------------------------------------------------------
__global__ void __launch_bounds__(256) k_comb(const float* __restrict__ wb1,
                                              const float* __restrict__ wb2,
                                              const int*   __restrict__ ui,
                                              const int*   __restrict__ ii,
                                              const int*   __restrict__ ni,
                                              float*       __restrict__ out) {
    int t = blockIdx.x * blockDim.x + threadIdx.x;
    int row = t >> 4, q = t & 15;
    if (row >= 3 * BATCH) return;
    int seg = row / BATCH, b = row % BATCH;

    const int*   idxA = (seg == 0) ? ui : ((seg == 1) ? ii : ni);
    const float* wbp  = (seg == 0) ? wb1 : wb2;
    int roff = (seg == 0) ? 0 : NU;

    int id = g_rowid[roff + __ldg(idxA + b)];
    float w0 = __ldg(wbp + 0), w1 = __ldg(wbp + 1), w2 = __ldg(wbp + 2);

    const float* mb = g_m + (size_t)id * NP * D + q * 4;
    float4 m0 = *reinterpret_cast<const float4*>(mb);
    float4 m1 = *reinterpret_cast<const float4*>(mb + D);
    float4 m2 = *reinterpret_cast<const float4*>(mb + 2 * D);

    float4 o;
    o.x = fmaxf(w0 * fmaxf(m0.x, 0.f) + w1 * fmaxf(m1.x, 0.f) + w2 * fmaxf(m2.x, 0.f), 0.f);
    o.y = fmaxf(w0 * fmaxf(m0.y, 0.f) + w1 * fmaxf(m1.y, 0.f) + w2 * fmaxf(m2.y, 0.f), 0.f);
    o.z = fmaxf(w0 * fmaxf(m0.z, 0.f) + w1 * fmaxf(m1.z, 0.f) + w2 * fmaxf(m2.z, 0.f), 0.f);
    o.w = fmaxf(w0 * fmaxf(m0.w, 0.f) + w1 * fmaxf(m1.w, 0.f) + w2 * fmaxf(m2.w, 0.f), 0.f);

    *reinterpret_cast<float4*>(out + ((size_t)seg * BATCH + b) * D + q * 4) = o;
}

// ---------------------------------------------------------------------------
// Launch
// ---------------------------------------------------------------------------
extern "C" void kernel_launch(void* const* d_in, const int* in_sizes, int n_in,
                              void* d_out, int out_size) {
    const float* user_table = (const float*)d_in[0];
    const float* item_table = (const float*)d_in[1];
    const float* Wu         = (const float*)d_in[2];
    const float* Wi         = (const float*)d_in[3];
    const float* wb1        = (const float*)d_in[4];
    const float* wb2        = (const float*)d_in[5];
    const float* user_vals  = (const float*)d_in[6];
    const float* item_vals  = (const float*)d_in[7];
    const int*   user_rows  = (const int*)d_in[8];
    const int*   user_cols  = (const int*)d_in[9];
    const int*   item_rows  = (const int*)d_in[10];
    const int*   item_cols  = (const int*)d_in[11];
    const int*   user_idx   = (const int*)d_in[12];
    const int*   item_idx   = (const int*)d_in[13];
    const int*   neg_idx    = (const int*)d_in[14];
    float* out = (float*)d_out;

    k_clear<<<cdiv(NU + NI + BMW + MAXSLOTS, 256), 256>>>();
    k_flags<<<cdiv(3 * BATCH, 256), 256>>>(user_idx, item_idx, neg_idx);
    k_bin<<<1184, 256>>>(user_rows, user_cols, user_vals,
                         item_rows, item_cols, item_vals);
    k_process<<<cdiv(MAXSLOTS, 4), 128>>>(user_table, item_table);
    k_gemm<<<(MAXROWS / TROWS) * NP, 256>>>(Wu, Wi);
    k_comb<<<cdiv(3 * BATCH * 16, 256), 256>>>(wb1, wb2, user_idx, item_idx, neg_idx, out);
}